// round 9
// baseline (speedup 1.0000x reference)
#include <cuda_runtime.h>
#include <cuda_bf16.h>
#include <math.h>

#define NPTS 16384
#define KNN  16
#define G    12
#define GC   (G * G * G)     // 1728 cells, ~9.5 pts/cell
#define HCELL (1.0f / G)
#define FULLM 0xffffffffu

// ---------------- scratch (device globals, no allocations) ----------------
__device__ float4 d_pts4[NPTS];
__device__ float  d_ptsPad[NPTS * 16];
__device__ float  d_imfT[NPTS * 32];
__device__ float  d_T1[16 * 64];
__device__ float  d_T2[64 * 128];
__device__ float  d_T3[32 * 64];
__device__ float  d_T4[64 * 128];
__device__ float  d_T5[128 * 256];
__device__ float  d_T6[256 * 128];
__device__ float  d_T7[416 * 32];
__device__ float  d_t1[NPTS * 64];
__device__ float  d_cf[NPTS * 128];
__device__ float  d_t2[NPTS * 64];
__device__ float  d_g [NPTS * 128];
__device__ float  d_h1[NPTS * 256];
__device__ float  d_h [NPTS * 128];
__device__ int    d_knn[NPTS * KNN];
// grid: [0:GC)=counts, [GC:2GC)=scatter cursors. Zero at module load; final_kernel
// re-zeroes every invocation, so they are always zero on entry.
__device__ int    d_cellCnt[2 * GC];
__device__ int    d_cellStart[GC + 1];
__device__ int    d_ptCell[NPTS];
__device__ float4 d_spts[NPTS];
__device__ int    d_sidx[NPTS];

__device__ __forceinline__ float lrelu(float x) { return x > 0.f ? x : 0.01f * x; }

// ---------------- hist: ONLY what the KNN chain needs (critical path) ----------------
__global__ void hist_kernel(const float* __restrict__ cloud)
{
    const int n = blockIdx.x * blockDim.x + threadIdx.x;
    if (n >= NPTS) return;
    float x = cloud[n * 3 + 0], y = cloud[n * 3 + 1], z = cloud[n * 3 + 2];
    d_pts4[n] = make_float4(x, y, z, x * x + y * y + z * z);
    int cx = min(G - 1, max(0, (int)(x * G)));
    int cy = min(G - 1, max(0, (int)(y * G)));
    int cz = min(G - 1, max(0, (int)(z * G)));
    int c = (cz * G + cy) * G + cx;
    d_ptCell[n] = c;
    atomicAdd(&d_cellCnt[c], 1);
}

// ---------------- prep2 (side stream): transposes + ptsPad ----------------
__global__ void __launch_bounds__(256) prep2_kernel(const float* __restrict__ img,
                                                    const float* __restrict__ cloud,
                                                    const float* __restrict__ c1w, const float* __restrict__ c2w,
                                                    const float* __restrict__ ps1w, const float* __restrict__ ps2w,
                                                    const float* __restrict__ pc1w, const float* __restrict__ pc2w,
                                                    const float* __restrict__ finw)
{
    __shared__ float tile[32][33];
    const int tid = threadIdx.x;
    const int stride = gridDim.x * blockDim.x;
    const int i0 = blockIdx.x * blockDim.x + tid;

    // img [32, NPTS] -> imfT [NPTS, 32], smem-tiled, coalesced both sides
    for (int t = blockIdx.x; t < NPTS / 32; t += gridDim.x) {
        const int n0 = t * 32;
        #pragma unroll
        for (int r8 = 0; r8 < 32; r8 += 8) {
            const int ch = (tid >> 5) + r8, nn = tid & 31;
            tile[ch][nn] = img[ch * NPTS + n0 + nn];
        }
        __syncthreads();
        #pragma unroll
        for (int r8 = 0; r8 < 32; r8 += 8) {
            const int nn = (tid >> 5) + r8, ch = tid & 31;
            d_imfT[(n0 + nn) * 32 + ch] = tile[ch][nn];
        }
        __syncthreads();
    }

    for (int n = i0; n < NPTS; n += stride) {
        float x = cloud[n * 3 + 0], y = cloud[n * 3 + 1], z = cloud[n * 3 + 2];
        float* row = &d_ptsPad[n * 16];
        row[0] = x; row[1] = y; row[2] = z;
        #pragma unroll
        for (int k = 3; k < 16; k++) row[k] = 0.f;
    }
    for (int t = i0; t < 16 * 64; t += stride) {
        int k = t >> 6, j = t & 63;
        d_T1[t] = (k < 3) ? pc1w[j * 3 + k] : 0.f;
    }
    for (int t = i0; t < 64 * 128; t += stride) { int k = t >> 7, c = t & 127; d_T2[t] = pc2w[c * 64 + k]; }
    for (int t = i0; t < 32 * 64;  t += stride) { int k = t >> 6, j = t & 63;  d_T3[t] = c1w[j * 32 + k]; }
    for (int t = i0; t < 64 * 128; t += stride) { int k = t >> 7, c = t & 127; d_T4[t] = c2w[c * 64 + k]; }
    for (int t = i0; t < 128 * 256; t += stride) { int k = t >> 8, c = t & 255; d_T5[t] = ps1w[c * 128 + k]; }
    for (int t = i0; t < 256 * 128; t += stride) { int k = t >> 7, c = t & 127; d_T6[t] = ps2w[c * 256 + k]; }
    for (int t = i0; t < 416 * 32;  t += stride) { int c = t >> 5, j = t & 31;  d_T7[t] = finw[j * 416 + c]; }
}

// ---------------- grid build ----------------
__global__ void scan_kernel()   // one block, 512 threads, 1728 cells
{
    __shared__ int ssum[512];
    const int t = threadIdx.x;
    int c0 = 0, c1 = 0, c2 = 0, c3 = 0;
    if (4 * t < GC) {
        c0 = d_cellCnt[4 * t + 0]; c1 = d_cellCnt[4 * t + 1];
        c2 = d_cellCnt[4 * t + 2]; c3 = d_cellCnt[4 * t + 3];
    }
    int s = c0 + c1 + c2 + c3;
    ssum[t] = s;
    __syncthreads();
    for (int off = 1; off < 512; off <<= 1) {
        int v = (t >= off) ? ssum[t - off] : 0;
        __syncthreads();
        ssum[t] += v;
        __syncthreads();
    }
    int excl = ssum[t] - s;
    if (4 * t < GC) {
        d_cellStart[4 * t + 0] = excl;
        d_cellStart[4 * t + 1] = excl + c0;
        d_cellStart[4 * t + 2] = excl + c0 + c1;
        d_cellStart[4 * t + 3] = excl + c0 + c1 + c2;
    }
    if (t == 511) d_cellStart[GC] = ssum[511];
}

__global__ void scatter_kernel()
{
    const int n = blockIdx.x * blockDim.x + threadIdx.x;
    if (n >= NPTS) return;
    const int c = d_ptCell[n];
    const int pos = d_cellStart[c] + atomicAdd(&d_cellCnt[GC + c], 1);
    d_spts[pos] = d_pts4[n];
    d_sidx[pos] = n;
}

// ---------------- KNN: one WARP per query, distributed top-16 ----------------
__device__ __forceinline__ void warp_scan_range(int st, int en, int lane,
                                                float qx, float qy, float qz,
                                                float& e, int& ei, float& thresh)
{
    const int nb = (en - st + 31) >> 5;
    for (int b = 0; b < nb; b++) {
        const int p = st + (b << 5) + lane;
        float dcand = INFINITY;
        if (p < en) {
            const float4 c = d_spts[p];
            const float dx = qx - c.x, dy = qy - c.y, dz = qz - c.z;
            dcand = fmaf(dx, dx, fmaf(dy, dy, dz * dz));
        }
        unsigned mask = __ballot_sync(FULLM, dcand <= thresh);
        while (mask) {
            const int src = __ffs(mask) - 1;
            mask &= mask - 1;
            const float v = __shfl_sync(FULLM, dcand, src);
            const int  vi = __shfl_sync(FULLM, p,     src);
            if (v <= thresh) {              // uniform
                const unsigned le = __ballot_sync(FULLM, e <= v) & 0xFFFFu;
                const int pos = __popc(le);
                const float pe = __shfl_up_sync(FULLM, e, 1);
                const int  pei = __shfl_up_sync(FULLM, ei, 1);
                if (lane > pos) { e = pe; ei = pei; }
                if (lane == pos) { e = v; ei = vi; }
                thresh = fminf(thresh, __shfl_sync(FULLM, e, 15));
            }
        }
    }
}

__global__ void __launch_bounds__(256) knn_warp_kernel()
{
    const int lane = threadIdx.x & 31;
    const int s = (blockIdx.x * 256 + threadIdx.x) >> 5;   // query = sorted position
    const float4 pq = d_spts[s];
    const int cx = min(G - 1, max(0, (int)(pq.x * G)));
    const int cy = min(G - 1, max(0, (int)(pq.y * G)));
    const int cz = min(G - 1, max(0, (int)(pq.z * G)));

    float e = INFINITY; int ei = 0;
    // seed thresh: provable upper bound on kd15 from 32 sorted-order neighbors
    float thresh;
    {
        const int base = min(max(s - 15, 0), NPTS - 32);
        const float4 c = d_spts[base + lane];
        const float dx = pq.x - c.x, dy = pq.y - c.y, dz = pq.z - c.z;
        float v = fmaf(dx, dx, fmaf(dy, dy, dz * dz));
        const int local = lane & 7;
        {
            float o; bool lower, asc;
            o = __shfl_xor_sync(FULLM, v, 1); lower = !(local & 1); asc = !(local & 2);
            v = (lower == asc) ? fminf(v, o) : fmaxf(v, o);
            o = __shfl_xor_sync(FULLM, v, 2); lower = !(local & 2); asc = !(local & 4);
            v = (lower == asc) ? fminf(v, o) : fmaxf(v, o);
            o = __shfl_xor_sync(FULLM, v, 1); lower = !(local & 1); asc = !(local & 4);
            v = (lower == asc) ? fminf(v, o) : fmaxf(v, o);
            o = __shfl_xor_sync(FULLM, v, 4); lower = !(local & 4);
            v = lower ? fminf(v, o) : fmaxf(v, o);
            o = __shfl_xor_sync(FULLM, v, 2); lower = !(local & 2);
            v = lower ? fminf(v, o) : fmaxf(v, o);
            o = __shfl_xor_sync(FULLM, v, 1); lower = !(local & 1);
            v = lower ? fminf(v, o) : fmaxf(v, o);
        }
        float m3 = __shfl_sync(FULLM, v, (lane & ~7) + 3);   // group's 4th smallest
        m3 = fmaxf(m3, __shfl_xor_sync(FULLM, m3, 8));
        m3 = fmaxf(m3, __shfl_xor_sync(FULLM, m3, 16));
        thresh = m3;
    }

    for (int m = 0; m < G; m++) {
        const int x0 = max(cx - m, 0), x1 = min(cx + m, G - 1);
        const int y0 = max(cy - m, 0), y1 = min(cy + m, G - 1);
        const int z0 = max(cz - m, 0), z1 = min(cz + m, G - 1);
        for (int z = z0; z <= z1; z++) {
            const bool zs = (z == cz - m) || (z == cz + m);
            for (int y = y0; y <= y1; y++) {
                const bool edge = zs || (y == cy - m) || (y == cy + m);
                const int rowc = (z * G + y) * G;
                if (edge) {
                    warp_scan_range(d_cellStart[rowc + x0], d_cellStart[rowc + x1 + 1],
                                    lane, pq.x, pq.y, pq.z, e, ei, thresh);
                } else {
                    if (cx - m >= 0)
                        warp_scan_range(d_cellStart[rowc + cx - m], d_cellStart[rowc + cx - m + 1],
                                        lane, pq.x, pq.y, pq.z, e, ei, thresh);
                    if (cx + m <= G - 1)
                        warp_scan_range(d_cellStart[rowc + cx + m], d_cellStart[rowc + cx + m + 1],
                                        lane, pq.x, pq.y, pq.z, e, ei, thresh);
                }
            }
        }
        const float bound = (float)m * HCELL;
        const float e15 = __shfl_sync(FULLM, e, 15);
        if (e15 < bound * bound) break;
    }

    if (lane < KNN) {
        const int orig = d_sidx[s];
        d_knn[orig * KNN + lane] = d_sidx[ei];
    }
}

// ---------------- generic fp32 GEMM ----------------
__global__ void __launch_bounds__(256) gemm_kernel(const float* __restrict__ A,
                                                   const float* __restrict__ Bt,
                                                   const float* __restrict__ bias,
                                                   float* __restrict__ C,
                                                   int K, int Nc, int act)
{
    __shared__ float As[16][68];
    __shared__ float Bs[16][64];
    const int tid  = threadIdx.x;
    const int tcol = tid & 15, trow = tid >> 4;
    const int m0 = blockIdx.y * 64, n0 = blockIdx.x * 64;
    const int lmA = tid >> 2, lkA = (tid & 3) << 2;
    const int lkB = tid >> 4, lnB = (tid & 15) << 2;

    float acc[4][4];
    #pragma unroll
    for (int i = 0; i < 4; i++)
        #pragma unroll
        for (int j = 0; j < 4; j++) acc[i][j] = 0.f;

    for (int k0 = 0; k0 < K; k0 += 16) {
        float4 a = *(const float4*)&A[(m0 + lmA) * K + k0 + lkA];
        As[lkA + 0][lmA] = a.x; As[lkA + 1][lmA] = a.y;
        As[lkA + 2][lmA] = a.z; As[lkA + 3][lmA] = a.w;
        *(float4*)&Bs[lkB][lnB] = *(const float4*)&Bt[(k0 + lkB) * Nc + n0 + lnB];
        __syncthreads();
        #pragma unroll
        for (int k = 0; k < 16; k++) {
            float4 av = *(const float4*)&As[k][trow << 2];
            float4 bv = *(const float4*)&Bs[k][tcol << 2];
            float ar[4] = {av.x, av.y, av.z, av.w};
            float br[4] = {bv.x, bv.y, bv.z, bv.w};
            #pragma unroll
            for (int i = 0; i < 4; i++)
                #pragma unroll
                for (int j = 0; j < 4; j++)
                    acc[i][j] = fmaf(ar[i], br[j], acc[i][j]);
        }
        __syncthreads();
    }

    float4 bb = *(const float4*)&bias[n0 + (tcol << 2)];
    const float bbr[4] = {bb.x, bb.y, bb.z, bb.w};
    #pragma unroll
    for (int i = 0; i < 4; i++) {
        const int m = m0 + (trow << 2) + i;
        float4 r;
        float v0 = acc[i][0] + bbr[0], v1 = acc[i][1] + bbr[1];
        float v2 = acc[i][2] + bbr[2], v3 = acc[i][3] + bbr[3];
        if (act) { v0 = lrelu(v0); v1 = lrelu(v1); v2 = lrelu(v2); v3 = lrelu(v3); }
        r.x = v0; r.y = v1; r.z = v2; r.w = v3;
        *(float4*)&C[m * Nc + n0 + (tcol << 2)] = r;
    }
}

// ---------------- final (+ re-zero grid counters for next invocation) ----------------
__global__ void __launch_bounds__(256) final_kernel(const float* __restrict__ img,
                                                    const float* __restrict__ fb,
                                                    float* __restrict__ out)
{
    __shared__ float swgt[8][KNN];
    __shared__ int   sidx[8][KNN];
    __shared__ float sfin[8][416];
    const int w = threadIdx.x >> 5, lane = threadIdx.x & 31;
    const int n = blockIdx.x * 8 + w;

    for (int t = blockIdx.x * blockDim.x + threadIdx.x; t < 2 * GC; t += gridDim.x * blockDim.x)
        d_cellCnt[t] = 0;

    const float4 pq = d_pts4[n];
    float negd = -INFINITY; int myi = 0;
    if (lane < KNN) {
        myi = d_knn[n * KNN + lane];
        float4 pc = d_pts4[myi];
        float dx = pq.x - pc.x, dy = pq.y - pc.y, dz = pq.z - pc.z;
        negd = -sqrtf(fmaxf(dx * dx + dy * dy + dz * dz, 1e-12f));
    }
    float m = negd;
    #pragma unroll
    for (int s = 16; s > 0; s >>= 1) m = fmaxf(m, __shfl_xor_sync(0xffffffffu, m, s));
    float e = (lane < KNN) ? expf(negd - m) : 0.f;
    float ss = e;
    #pragma unroll
    for (int s = 16; s > 0; s >>= 1) ss += __shfl_xor_sync(0xffffffffu, ss, s);
    if (lane < KNN) { swgt[w][lane] = e / ss; sidx[w][lane] = myi; }
    __syncwarp();

    float4 sf = make_float4(-INFINITY, -INFINITY, -INFINITY, -INFINITY);
    float4 sp = make_float4(-INFINITY, -INFINITY, -INFINITY, -INFINITY);
    #pragma unroll
    for (int k = 0; k < KNN; k++) {
        const int ik = sidx[w][k];
        const float wk = swgt[w][k];
        const float4 gv = *(const float4*)&d_g[ik * 128 + (lane << 2)];
        const float4 hv = *(const float4*)&d_h[ik * 128 + (lane << 2)];
        sf.x = fmaxf(sf.x, gv.x * wk); sf.y = fmaxf(sf.y, gv.y * wk);
        sf.z = fmaxf(sf.z, gv.z * wk); sf.w = fmaxf(sf.w, gv.w * wk);
        sp.x = fmaxf(sp.x, hv.x * wk); sp.y = fmaxf(sp.y, hv.y * wk);
        sp.z = fmaxf(sp.z, hv.z * wk); sp.w = fmaxf(sp.w, hv.w * wk);
    }
    const int c4 = lane << 2;
    sfin[w][c4 + 0] = lrelu(sp.x); sfin[w][c4 + 1] = lrelu(sp.y);
    sfin[w][c4 + 2] = lrelu(sp.z); sfin[w][c4 + 3] = lrelu(sp.w);
    sfin[w][128 + lane] = lrelu(img[lane * NPTS + n]);
    sfin[w][160 + c4 + 0] = lrelu(sf.x); sfin[w][160 + c4 + 1] = lrelu(sf.y);
    sfin[w][160 + c4 + 2] = lrelu(sf.z); sfin[w][160 + c4 + 3] = lrelu(sf.w);
    const float4 cv = *(const float4*)&d_cf[n * 128 + c4];
    sfin[w][288 + c4 + 0] = lrelu(cv.x); sfin[w][288 + c4 + 1] = lrelu(cv.y);
    sfin[w][288 + c4 + 2] = lrelu(cv.z); sfin[w][288 + c4 + 3] = lrelu(cv.w);
    __syncwarp();

    float acc = fb[lane];
    #pragma unroll 8
    for (int c = 0; c < 416; c++)
        acc = fmaf(sfin[w][c], d_T7[c * 32 + lane], acc);
    out[lane * NPTS + n] = acc;
}

// ---------------- launch ----------------
extern "C" void kernel_launch(void* const* d_in, const int* in_sizes, int n_in,
                              void* d_out, int out_size)
{
    const float* img   = (const float*)d_in[0];
    const float* cloud = (const float*)d_in[1];
    const float* c1w  = (const float*)d_in[2];  const float* c1b  = (const float*)d_in[3];
    const float* c2w  = (const float*)d_in[4];  const float* c2b  = (const float*)d_in[5];
    const float* ps1w = (const float*)d_in[6];  const float* ps1b = (const float*)d_in[7];
    const float* ps2w = (const float*)d_in[8];  const float* ps2b = (const float*)d_in[9];
    const float* pc1w = (const float*)d_in[10]; const float* pc1b = (const float*)d_in[11];
    const float* pc2w = (const float*)d_in[12]; const float* pc2b = (const float*)d_in[13];
    const float* finw = (const float*)d_in[14]; const float* finb = (const float*)d_in[15];
    float* out = (float*)d_out;

    void *pPtsPad, *pT1, *pT2, *pT3, *pT4, *pT5, *pT6;
    void *pt1, *pcf, *pimfT, *pt2, *pg, *ph1, *ph;
    cudaGetSymbolAddress(&pPtsPad, d_ptsPad);
    cudaGetSymbolAddress(&pT1, d_T1); cudaGetSymbolAddress(&pT2, d_T2);
    cudaGetSymbolAddress(&pT3, d_T3); cudaGetSymbolAddress(&pT4, d_T4);
    cudaGetSymbolAddress(&pT5, d_T5); cudaGetSymbolAddress(&pT6, d_T6);
    cudaGetSymbolAddress(&pt1, d_t1); cudaGetSymbolAddress(&pcf, d_cf);
    cudaGetSymbolAddress(&pimfT, d_imfT); cudaGetSymbolAddress(&pt2, d_t2);
    cudaGetSymbolAddress(&pg, d_g); cudaGetSymbolAddress(&ph1, d_h1);
    cudaGetSymbolAddress(&ph, d_h);

    static cudaStream_t s1 = nullptr;
    static cudaEvent_t evFork = nullptr, evJoin = nullptr;
    if (s1 == nullptr) {
        cudaStreamCreateWithFlags(&s1, cudaStreamNonBlocking);
        cudaEventCreateWithFlags(&evFork, cudaEventDisableTiming);
        cudaEventCreateWithFlags(&evJoin, cudaEventDisableTiming);
    }

    // fork side stream at t=0 (prep2/GEMMs depend only on inputs)
    cudaEventRecord(evFork, 0);

    // main stream: hist -> scan -> scatter -> knn   (knn = my 4th kernel)
    hist_kernel<<<NPTS / 256, 256>>>(cloud);
    scan_kernel<<<1, 512>>>();
    scatter_kernel<<<NPTS / 256, 256>>>();
    knn_warp_kernel<<<NPTS * 32 / 256, 256>>>();

    // side stream: prep2 then GEMM chain, overlapping the whole KNN path
    cudaStreamWaitEvent(s1, evFork, 0);
    prep2_kernel<<<256, 256, 0, s1>>>(img, cloud, c1w, c2w, ps1w, ps2w, pc1w, pc2w, finw);
    gemm_kernel<<<dim3(1, NPTS / 64), 256, 0, s1>>>((const float*)pPtsPad, (const float*)pT1, pc1b, (float*)pt1, 16, 64, 1);
    gemm_kernel<<<dim3(2, NPTS / 64), 256, 0, s1>>>((const float*)pt1, (const float*)pT2, pc2b, (float*)pcf, 64, 128, 0);
    gemm_kernel<<<dim3(1, NPTS / 64), 256, 0, s1>>>((const float*)pimfT, (const float*)pT3, c1b, (float*)pt2, 32, 64, 1);
    gemm_kernel<<<dim3(2, NPTS / 64), 256, 0, s1>>>((const float*)pt2, (const float*)pT4, c2b, (float*)pg, 64, 128, 0);
    gemm_kernel<<<dim3(4, NPTS / 64), 256, 0, s1>>>((const float*)pcf, (const float*)pT5, ps1b, (float*)ph1, 128, 256, 1);
    gemm_kernel<<<dim3(2, NPTS / 64), 256, 0, s1>>>((const float*)ph1, (const float*)pT6, ps2b, (float*)ph, 256, 128, 0);
    cudaEventRecord(evJoin, s1);

    // join, then final
    cudaStreamWaitEvent(0, evJoin, 0);
    final_kernel<<<NPTS / 8, 256>>>(img, finb, out);
}

// round 10
// speedup vs baseline: 1.0666x; 1.0666x over previous
#include <cuda_runtime.h>
#include <cuda_bf16.h>
#include <math.h>

#define NPTS 16384
#define KNN  16
#define G    12
#define GC   (G * G * G)     // 1728 cells, ~9.5 pts/cell
#define HCELL (1.0f / G)
#define FULLM 0xffffffffu

// ---------------- scratch (device globals, no allocations) ----------------
__device__ float4 d_pts4[NPTS];
__device__ float  d_T7[416 * 32];
__device__ float  d_cf[NPTS * 128];
__device__ float  d_g [NPTS * 128];
__device__ float  d_h [NPTS * 128];
__device__ int    d_knn[NPTS * KNN];
__device__ int    d_cellStart[GC + 1];
__device__ int    d_ptCell[NPTS];
__device__ float4 d_spts[NPTS];
__device__ int    d_sidx[NPTS];

__device__ __forceinline__ float lrelu(float x) { return x > 0.f ? x : 0.01f * x; }

// ---------------- gridbuild: hist + scan + scatter + T7, ONE block ----------------
__global__ void __launch_bounds__(1024) gridbuild_kernel(const float* __restrict__ cloud,
                                                         const float* __restrict__ finw)
{
    __shared__ int scnt[GC];
    __shared__ int ssum[512];
    const int tid = threadIdx.x;

    for (int c = tid; c < GC; c += 1024) scnt[c] = 0;
    __syncthreads();

    // hist + pts4
    for (int n = tid; n < NPTS; n += 1024) {
        float x = cloud[n * 3 + 0], y = cloud[n * 3 + 1], z = cloud[n * 3 + 2];
        d_pts4[n] = make_float4(x, y, z, x * x + y * y + z * z);
        int cx = min(G - 1, max(0, (int)(x * G)));
        int cy = min(G - 1, max(0, (int)(y * G)));
        int cz = min(G - 1, max(0, (int)(z * G)));
        int c = (cz * G + cy) * G + cx;
        d_ptCell[n] = c;
        atomicAdd(&scnt[c], 1);
    }
    __syncthreads();

    // scan of 1728 cells by threads 0..431 (4 cells each), block-scan over 512
    int c0 = 0, c1 = 0, c2 = 0, c3 = 0, s = 0;
    if (tid < 512) {
        if (4 * tid < GC) {
            c0 = scnt[4 * tid + 0]; c1 = scnt[4 * tid + 1];
            c2 = scnt[4 * tid + 2]; c3 = scnt[4 * tid + 3];
        }
        s = c0 + c1 + c2 + c3;
        ssum[tid] = s;
    }
    __syncthreads();
    for (int off = 1; off < 512; off <<= 1) {
        int v = 0;
        if (tid < 512 && tid >= off) v = ssum[tid - off];
        __syncthreads();
        if (tid < 512) ssum[tid] += v;
        __syncthreads();
    }
    if (tid < 512 && 4 * tid < GC) {
        int excl = ssum[tid] - s;
        d_cellStart[4 * tid + 0] = excl;
        d_cellStart[4 * tid + 1] = excl + c0;
        d_cellStart[4 * tid + 2] = excl + c0 + c1;
        d_cellStart[4 * tid + 3] = excl + c0 + c1 + c2;
        // reuse scnt as scatter cursors (running starts)
        scnt[4 * tid + 0] = excl;
        scnt[4 * tid + 1] = excl + c0;
        scnt[4 * tid + 2] = excl + c0 + c1;
        scnt[4 * tid + 3] = excl + c0 + c1 + c2;
    }
    if (tid == 511) d_cellStart[GC] = ssum[511];
    __syncthreads();

    // scatter
    for (int n = tid; n < NPTS; n += 1024) {
        const int c = d_ptCell[n];
        const int pos = atomicAdd(&scnt[c], 1);
        d_spts[pos] = d_pts4[n];
        d_sidx[pos] = n;
    }

    // T7 transpose: finw [32,416] -> [416,32]
    for (int t = tid; t < 416 * 32; t += 1024) {
        int c = t >> 5, j = t & 31;
        d_T7[t] = finw[j * 416 + c];
    }
}

// ---------------- KNN: one WARP per query, distributed top-16 ----------------
__device__ __forceinline__ void warp_scan_range(int st, int en, int lane,
                                                float qx, float qy, float qz,
                                                float& e, int& ei, float& thresh)
{
    const int nb = (en - st + 31) >> 5;
    for (int b = 0; b < nb; b++) {
        const int p = st + (b << 5) + lane;
        float dcand = INFINITY;
        if (p < en) {
            const float4 c = d_spts[p];
            const float dx = qx - c.x, dy = qy - c.y, dz = qz - c.z;
            dcand = fmaf(dx, dx, fmaf(dy, dy, dz * dz));
        }
        unsigned mask = __ballot_sync(FULLM, dcand <= thresh);
        while (mask) {
            const int src = __ffs(mask) - 1;
            mask &= mask - 1;
            const float v = __shfl_sync(FULLM, dcand, src);
            const int  vi = __shfl_sync(FULLM, p,     src);
            if (v <= thresh) {              // uniform
                const unsigned le = __ballot_sync(FULLM, e <= v) & 0xFFFFu;
                const int pos = __popc(le);
                const float pe = __shfl_up_sync(FULLM, e, 1);
                const int  pei = __shfl_up_sync(FULLM, ei, 1);
                if (lane > pos) { e = pe; ei = pei; }
                if (lane == pos) { e = v; ei = vi; }
                thresh = fminf(thresh, __shfl_sync(FULLM, e, 15));
            }
        }
    }
}

__global__ void __launch_bounds__(256) knn_warp_kernel()
{
    const int lane = threadIdx.x & 31;
    const int s = (blockIdx.x * 256 + threadIdx.x) >> 5;   // query = sorted position
    const float4 pq = d_spts[s];
    const int cx = min(G - 1, max(0, (int)(pq.x * G)));
    const int cy = min(G - 1, max(0, (int)(pq.y * G)));
    const int cz = min(G - 1, max(0, (int)(pq.z * G)));

    float e = INFINITY; int ei = 0;
    // seed thresh: provable upper bound on kd15 from 32 sorted-order neighbors
    float thresh;
    {
        const int base = min(max(s - 15, 0), NPTS - 32);
        const float4 c = d_spts[base + lane];
        const float dx = pq.x - c.x, dy = pq.y - c.y, dz = pq.z - c.z;
        float v = fmaf(dx, dx, fmaf(dy, dy, dz * dz));
        const int local = lane & 7;
        {
            float o; bool lower, asc;
            o = __shfl_xor_sync(FULLM, v, 1); lower = !(local & 1); asc = !(local & 2);
            v = (lower == asc) ? fminf(v, o) : fmaxf(v, o);
            o = __shfl_xor_sync(FULLM, v, 2); lower = !(local & 2); asc = !(local & 4);
            v = (lower == asc) ? fminf(v, o) : fmaxf(v, o);
            o = __shfl_xor_sync(FULLM, v, 1); lower = !(local & 1); asc = !(local & 4);
            v = (lower == asc) ? fminf(v, o) : fmaxf(v, o);
            o = __shfl_xor_sync(FULLM, v, 4); lower = !(local & 4);
            v = lower ? fminf(v, o) : fmaxf(v, o);
            o = __shfl_xor_sync(FULLM, v, 2); lower = !(local & 2);
            v = lower ? fminf(v, o) : fmaxf(v, o);
            o = __shfl_xor_sync(FULLM, v, 1); lower = !(local & 1);
            v = lower ? fminf(v, o) : fmaxf(v, o);
        }
        float m3 = __shfl_sync(FULLM, v, (lane & ~7) + 3);   // group's 4th smallest
        m3 = fmaxf(m3, __shfl_xor_sync(FULLM, m3, 8));
        m3 = fmaxf(m3, __shfl_xor_sync(FULLM, m3, 16));
        thresh = m3;
    }

    for (int m = 0; m < G; m++) {
        const int x0 = max(cx - m, 0), x1 = min(cx + m, G - 1);
        const int y0 = max(cy - m, 0), y1 = min(cy + m, G - 1);
        const int z0 = max(cz - m, 0), z1 = min(cz + m, G - 1);
        for (int z = z0; z <= z1; z++) {
            const bool zs = (z == cz - m) || (z == cz + m);
            for (int y = y0; y <= y1; y++) {
                const bool edge = zs || (y == cy - m) || (y == cy + m);
                const int rowc = (z * G + y) * G;
                if (edge) {
                    warp_scan_range(d_cellStart[rowc + x0], d_cellStart[rowc + x1 + 1],
                                    lane, pq.x, pq.y, pq.z, e, ei, thresh);
                } else {
                    if (cx - m >= 0)
                        warp_scan_range(d_cellStart[rowc + cx - m], d_cellStart[rowc + cx - m + 1],
                                        lane, pq.x, pq.y, pq.z, e, ei, thresh);
                    if (cx + m <= G - 1)
                        warp_scan_range(d_cellStart[rowc + cx + m], d_cellStart[rowc + cx + m + 1],
                                        lane, pq.x, pq.y, pq.z, e, ei, thresh);
                }
            }
        }
        const float bound = (float)m * HCELL;
        const float e15 = __shfl_sync(FULLM, e, 15);
        if (e15 < bound * bound) break;
    }

    if (lane < KNN) {
        const int orig = d_sidx[s];
        d_knn[orig * KNN + lane] = d_sidx[ei];
    }
}

// ---------------- fused MLP mega-kernel ----------------
// smem layout (dynamic): bufCf[128*68] | bufBig[256*68] | Bs[16*68]
// As0 staging area = bufBig + 192*68 (dead by the time bufBig[192..] is written)
#define PITCH 68
#define OFS_CF   0
#define OFS_BIG  (128 * PITCH)
#define OFS_BS   (384 * PITCH)
#define OFS_AS0  (OFS_BIG + 192 * PITCH)
#define SMEM_MLP (400 * PITCH * 4)

// C[64 x Nc] = act(A_smem^T(k-major) @ W^T + bias); W row-major [Nc, K] (K mult of 16,
// or k3pad: only first 3 k-rows real). Cs (channel-major, pitch 68) and/or gout [.,128].
__device__ void mlp_layer(const float* __restrict__ As, int K, int k3pad,
                          const float* __restrict__ W, const float* __restrict__ bias,
                          int Nc, int act, float* Cs, float* gout, int m0, float* Bs)
{
    const int tid = threadIdx.x;
    const int tcol = tid & 15, trow = tid >> 4;
    for (int n0 = 0; n0 < Nc; n0 += 64) {
        float acc[4][4];
        #pragma unroll
        for (int i = 0; i < 4; i++)
            #pragma unroll
            for (int j = 0; j < 4; j++) acc[i][j] = 0.f;

        for (int k0 = 0; k0 < K; k0 += 16) {
            __syncthreads();
            if (k3pad) {
                // W is [64 x 3]; pad k to 16 with zeros
                for (int idx = tid; idx < 16 * 64; idx += 256) {
                    int k = idx >> 6, n = idx & 63;
                    Bs[k * PITCH + n] = (k < 3) ? W[n * 3 + k] : 0.f;
                }
            } else {
                const int n = tid >> 2, kq = (tid & 3) << 2;
                const float4 w4 = *(const float4*)&W[(n0 + n) * K + k0 + kq];
                Bs[(kq + 0) * PITCH + n] = w4.x;
                Bs[(kq + 1) * PITCH + n] = w4.y;
                Bs[(kq + 2) * PITCH + n] = w4.z;
                Bs[(kq + 3) * PITCH + n] = w4.w;
            }
            __syncthreads();
            #pragma unroll
            for (int k = 0; k < 16; k++) {
                const float4 av = *(const float4*)&As[(k0 + k) * PITCH + (trow << 2)];
                const float4 bv = *(const float4*)&Bs[k * PITCH + (tcol << 2)];
                const float ar[4] = {av.x, av.y, av.z, av.w};
                const float br[4] = {bv.x, bv.y, bv.z, bv.w};
                #pragma unroll
                for (int i = 0; i < 4; i++)
                    #pragma unroll
                    for (int j = 0; j < 4; j++)
                        acc[i][j] = fmaf(ar[i], br[j], acc[i][j]);
            }
        }
        const float4 bb = *(const float4*)&bias[n0 + (tcol << 2)];
        const float bbr[4] = {bb.x, bb.y, bb.z, bb.w};
        #pragma unroll
        for (int i = 0; i < 4; i++) {
            float v[4];
            #pragma unroll
            for (int j = 0; j < 4; j++) {
                v[j] = acc[i][j] + bbr[j];
                if (act) v[j] = lrelu(v[j]);
            }
            if (gout) {
                float4 r; r.x = v[0]; r.y = v[1]; r.z = v[2]; r.w = v[3];
                *(float4*)&gout[(m0 + (trow << 2) + i) * 128 + n0 + (tcol << 2)] = r;
            }
            if (Cs) {
                #pragma unroll
                for (int j = 0; j < 4; j++)
                    Cs[(n0 + (tcol << 2) + j) * PITCH + (trow << 2) + i] = v[j];
            }
        }
    }
    __syncthreads();
}

__global__ void __launch_bounds__(256) mlp_kernel(
    const float* __restrict__ cloud, const float* __restrict__ img,
    const float* __restrict__ pc1w, const float* __restrict__ pc1b,
    const float* __restrict__ pc2w, const float* __restrict__ pc2b,
    const float* __restrict__ ps1w, const float* __restrict__ ps1b,
    const float* __restrict__ ps2w, const float* __restrict__ ps2b,
    const float* __restrict__ c1w,  const float* __restrict__ c1b,
    const float* __restrict__ c2w,  const float* __restrict__ c2b)
{
    extern __shared__ float smem[];
    float* bufCf  = smem + OFS_CF;
    float* bufBig = smem + OFS_BIG;
    float* Bs     = smem + OFS_BS;
    float* As0    = smem + OFS_AS0;
    const int tid = threadIdx.x;
    const int p0 = blockIdx.x * 64;
    float* pcf; float* pg; float* ph;
    {   // device-global outputs
        pcf = d_cf; pg = d_g; ph = d_h;
    }

    if (blockIdx.y == 0) {
        // point chain: pts(3) -> 64 (lrelu) -> cf(128) -> 256 (lrelu) -> h(128)
        for (int idx = tid; idx < 16 * 64; idx += 256) {
            int k = idx >> 6, m = idx & 63;
            As0[k * PITCH + m] = (k < 3) ? cloud[(p0 + m) * 3 + k] : 0.f;
        }
        mlp_layer(As0,    16, 1, pc1w, pc1b,  64, 1, bufBig, nullptr, p0, Bs);
        mlp_layer(bufBig, 64, 0, pc2w, pc2b, 128, 0, bufCf,  pcf,     p0, Bs);
        mlp_layer(bufCf, 128, 0, ps1w, ps1b, 256, 1, bufBig, nullptr, p0, Bs);
        mlp_layer(bufBig,256, 0, ps2w, ps2b, 128, 0, nullptr, ph,     p0, Bs);
    } else {
        // img chain: imf(32) -> 64 (lrelu) -> g(128); read img [32, NPTS] coalesced
        for (int idx = tid; idx < 32 * 64; idx += 256) {
            int k = idx >> 6, m = idx & 63;
            As0[k * PITCH + m] = img[k * NPTS + p0 + m];
        }
        mlp_layer(As0,    32, 0, c1w, c1b,  64, 1, bufBig, nullptr, p0, Bs);
        mlp_layer(bufBig, 64, 0, c2w, c2b, 128, 0, nullptr, pg,     p0, Bs);
    }
}

// ---------------- final: softmax weights, weighted max-pool, concat, GEMV ----------------
__global__ void __launch_bounds__(256) final_kernel(const float* __restrict__ img,
                                                    const float* __restrict__ fb,
                                                    float* __restrict__ out)
{
    __shared__ float swgt[8][KNN];
    __shared__ int   sidx[8][KNN];
    __shared__ float sfin[8][416];
    const int w = threadIdx.x >> 5, lane = threadIdx.x & 31;
    const int n = blockIdx.x * 8 + w;

    const float4 pq = d_pts4[n];
    float negd = -INFINITY; int myi = 0;
    if (lane < KNN) {
        myi = d_knn[n * KNN + lane];
        float4 pc = d_pts4[myi];
        float dx = pq.x - pc.x, dy = pq.y - pc.y, dz = pq.z - pc.z;
        negd = -sqrtf(fmaxf(dx * dx + dy * dy + dz * dz, 1e-12f));
    }
    float m = negd;
    #pragma unroll
    for (int s = 16; s > 0; s >>= 1) m = fmaxf(m, __shfl_xor_sync(0xffffffffu, m, s));
    float e = (lane < KNN) ? expf(negd - m) : 0.f;
    float ss = e;
    #pragma unroll
    for (int s = 16; s > 0; s >>= 1) ss += __shfl_xor_sync(0xffffffffu, ss, s);
    if (lane < KNN) { swgt[w][lane] = e / ss; sidx[w][lane] = myi; }
    __syncwarp();

    float4 sf = make_float4(-INFINITY, -INFINITY, -INFINITY, -INFINITY);
    float4 sp = make_float4(-INFINITY, -INFINITY, -INFINITY, -INFINITY);
    #pragma unroll
    for (int k = 0; k < KNN; k++) {
        const int ik = sidx[w][k];
        const float wk = swgt[w][k];
        const float4 gv = *(const float4*)&d_g[ik * 128 + (lane << 2)];
        const float4 hv = *(const float4*)&d_h[ik * 128 + (lane << 2)];
        sf.x = fmaxf(sf.x, gv.x * wk); sf.y = fmaxf(sf.y, gv.y * wk);
        sf.z = fmaxf(sf.z, gv.z * wk); sf.w = fmaxf(sf.w, gv.w * wk);
        sp.x = fmaxf(sp.x, hv.x * wk); sp.y = fmaxf(sp.y, hv.y * wk);
        sp.z = fmaxf(sp.z, hv.z * wk); sp.w = fmaxf(sp.w, hv.w * wk);
    }
    const int c4 = lane << 2;
    sfin[w][c4 + 0] = lrelu(sp.x); sfin[w][c4 + 1] = lrelu(sp.y);
    sfin[w][c4 + 2] = lrelu(sp.z); sfin[w][c4 + 3] = lrelu(sp.w);
    sfin[w][128 + lane] = lrelu(img[lane * NPTS + n]);
    sfin[w][160 + c4 + 0] = lrelu(sf.x); sfin[w][160 + c4 + 1] = lrelu(sf.y);
    sfin[w][160 + c4 + 2] = lrelu(sf.z); sfin[w][160 + c4 + 3] = lrelu(sf.w);
    const float4 cv = *(const float4*)&d_cf[n * 128 + c4];
    sfin[w][288 + c4 + 0] = lrelu(cv.x); sfin[w][288 + c4 + 1] = lrelu(cv.y);
    sfin[w][288 + c4 + 2] = lrelu(cv.z); sfin[w][288 + c4 + 3] = lrelu(cv.w);
    __syncwarp();

    float acc = fb[lane];
    #pragma unroll 8
    for (int c = 0; c < 416; c++)
        acc = fmaf(sfin[w][c], d_T7[c * 32 + lane], acc);
    out[lane * NPTS + n] = acc;
}

// ---------------- launch ----------------
extern "C" void kernel_launch(void* const* d_in, const int* in_sizes, int n_in,
                              void* d_out, int out_size)
{
    const float* img   = (const float*)d_in[0];
    const float* cloud = (const float*)d_in[1];
    const float* c1w  = (const float*)d_in[2];  const float* c1b  = (const float*)d_in[3];
    const float* c2w  = (const float*)d_in[4];  const float* c2b  = (const float*)d_in[5];
    const float* ps1w = (const float*)d_in[6];  const float* ps1b = (const float*)d_in[7];
    const float* ps2w = (const float*)d_in[8];  const float* ps2b = (const float*)d_in[9];
    const float* pc1w = (const float*)d_in[10]; const float* pc1b = (const float*)d_in[11];
    const float* pc2w = (const float*)d_in[12]; const float* pc2b = (const float*)d_in[13];
    const float* finw = (const float*)d_in[14]; const float* finb = (const float*)d_in[15];
    float* out = (float*)d_out;

    static cudaStream_t s1 = nullptr;
    static cudaEvent_t evFork = nullptr, evJoin = nullptr;
    if (s1 == nullptr) {
        cudaStreamCreateWithFlags(&s1, cudaStreamNonBlocking);
        cudaEventCreateWithFlags(&evFork, cudaEventDisableTiming);
        cudaEventCreateWithFlags(&evJoin, cudaEventDisableTiming);
        cudaFuncSetAttribute(mlp_kernel, cudaFuncAttributeMaxDynamicSharedMemorySize, SMEM_MLP);
    }

    // fork side stream at t=0 (mlp depends only on inputs)
    cudaEventRecord(evFork, 0);

    // main stream: gridbuild -> knn
    gridbuild_kernel<<<1, 1024>>>(cloud, finw);
    knn_warp_kernel<<<NPTS * 32 / 256, 256>>>();

    // side stream: fused 6-layer MLP (point chain + img chain)
    cudaStreamWaitEvent(s1, evFork, 0);
    mlp_kernel<<<dim3(NPTS / 64, 2), 256, SMEM_MLP, s1>>>(
        cloud, img, pc1w, pc1b, pc2w, pc2b, ps1w, ps1b, ps2w, ps2b,
        c1w, c1b, c2w, c2b);
    cudaEventRecord(evJoin, s1);

    // join, then final
    cudaStreamWaitEvent(0, evJoin, 0);
    final_kernel<<<NPTS / 8, 256>>>(img, finb, out);
}

// round 12
// speedup vs baseline: 1.0830x; 1.0154x over previous
#include <cuda_runtime.h>
#include <cuda_bf16.h>
#include <math.h>

#define NPTS 16384
#define KNN  16
#define G    12
#define GC   (G * G * G)     // 1728 cells, ~9.5 pts/cell
#define HCELL (1.0f / G)
#define FULLM 0xffffffffu

// ---------------- scratch (device globals, no allocations) ----------------
__device__ float4 d_pts4[NPTS];
__device__ float  d_T7v[104 * 32 * 4];   // (c4, j, q) <- finw[j][4*c4+q]
__device__ float  d_cf[NPTS * 128];
__device__ float  d_g [NPTS * 128];
__device__ float  d_h [NPTS * 128];
__device__ int    d_knn[NPTS * KNN];
__device__ float  d_wgt[NPTS * KNN];
__device__ int    d_cellStart[GC + 1];
__device__ int    d_ptCell[NPTS];
__device__ float4 d_spts[NPTS];
__device__ int    d_sidx[NPTS];

__device__ __forceinline__ float lrelu(float x) { return x > 0.f ? x : 0.01f * x; }

// ---------------- gridbuild: hist + scan + scatter + T7v, ONE block ----------------
__global__ void __launch_bounds__(1024) gridbuild_kernel(const float* __restrict__ cloud,
                                                         const float* __restrict__ finw)
{
    __shared__ int scnt[GC];
    __shared__ int ssum[512];
    const int tid = threadIdx.x;

    for (int c = tid; c < GC; c += 1024) scnt[c] = 0;
    __syncthreads();

    for (int n = tid; n < NPTS; n += 1024) {
        float x = cloud[n * 3 + 0], y = cloud[n * 3 + 1], z = cloud[n * 3 + 2];
        d_pts4[n] = make_float4(x, y, z, x * x + y * y + z * z);
        int cx = min(G - 1, max(0, (int)(x * G)));
        int cy = min(G - 1, max(0, (int)(y * G)));
        int cz = min(G - 1, max(0, (int)(z * G)));
        int c = (cz * G + cy) * G + cx;
        d_ptCell[n] = c;
        atomicAdd(&scnt[c], 1);
    }
    __syncthreads();

    int c0 = 0, c1 = 0, c2 = 0, c3 = 0, s = 0;
    if (tid < 512) {
        if (4 * tid < GC) {
            c0 = scnt[4 * tid + 0]; c1 = scnt[4 * tid + 1];
            c2 = scnt[4 * tid + 2]; c3 = scnt[4 * tid + 3];
        }
        s = c0 + c1 + c2 + c3;
        ssum[tid] = s;
    }
    __syncthreads();
    for (int off = 1; off < 512; off <<= 1) {
        int v = 0;
        if (tid < 512 && tid >= off) v = ssum[tid - off];
        __syncthreads();
        if (tid < 512) ssum[tid] += v;
        __syncthreads();
    }
    if (tid < 512 && 4 * tid < GC) {
        int excl = ssum[tid] - s;
        d_cellStart[4 * tid + 0] = excl;
        d_cellStart[4 * tid + 1] = excl + c0;
        d_cellStart[4 * tid + 2] = excl + c0 + c1;
        d_cellStart[4 * tid + 3] = excl + c0 + c1 + c2;
        scnt[4 * tid + 0] = excl;
        scnt[4 * tid + 1] = excl + c0;
        scnt[4 * tid + 2] = excl + c0 + c1;
        scnt[4 * tid + 3] = excl + c0 + c1 + c2;
    }
    if (tid == 511) d_cellStart[GC] = ssum[511];
    __syncthreads();

    for (int n = tid; n < NPTS; n += 1024) {
        const int c = d_ptCell[n];
        const int pos = atomicAdd(&scnt[c], 1);
        d_spts[pos] = d_pts4[n];
        d_sidx[pos] = n;
    }

    // T7v: finw [32,416] -> [104][32][4]
    for (int t = tid; t < 104 * 32 * 4; t += 1024) {
        int c4 = t >> 7, j = (t >> 2) & 31, q = t & 3;
        d_T7v[t] = finw[j * 416 + (c4 << 2) + q];
    }
}

// ---------------- KNN: one WARP per query, distributed top-16 + softmax ----------------
__device__ __forceinline__ void warp_scan_range(int st, int en, int lane,
                                                float qx, float qy, float qz,
                                                float& e, int& ei, float& thresh)
{
    const int nb = (en - st + 31) >> 5;
    for (int b = 0; b < nb; b++) {
        const int p = st + (b << 5) + lane;
        float dcand = INFINITY;
        if (p < en) {
            const float4 c = d_spts[p];
            const float dx = qx - c.x, dy = qy - c.y, dz = qz - c.z;
            dcand = fmaf(dx, dx, fmaf(dy, dy, dz * dz));
        }
        unsigned mask = __ballot_sync(FULLM, dcand <= thresh);
        while (mask) {
            const int src = __ffs(mask) - 1;
            mask &= mask - 1;
            const float v = __shfl_sync(FULLM, dcand, src);
            const int  vi = __shfl_sync(FULLM, p,     src);
            if (v <= thresh) {              // uniform
                const unsigned le = __ballot_sync(FULLM, e <= v) & 0xFFFFu;
                const int pos = __popc(le);
                const float pe = __shfl_up_sync(FULLM, e, 1);
                const int  pei = __shfl_up_sync(FULLM, ei, 1);
                if (lane > pos) { e = pe; ei = pei; }
                if (lane == pos) { e = v; ei = vi; }
                thresh = fminf(thresh, __shfl_sync(FULLM, e, 15));
            }
        }
    }
}

__global__ void __launch_bounds__(256) knn_warp_kernel()
{
    const int lane = threadIdx.x & 31;
    const int s = (blockIdx.x * 256 + threadIdx.x) >> 5;   // query = sorted position
    const float4 pq = d_spts[s];
    const int cx = min(G - 1, max(0, (int)(pq.x * G)));
    const int cy = min(G - 1, max(0, (int)(pq.y * G)));
    const int cz = min(G - 1, max(0, (int)(pq.z * G)));

    float e = INFINITY; int ei = 0;
    // seed thresh: provable upper bound on kd15 from 32 sorted-order neighbors
    float thresh;
    {
        const int base = min(max(s - 15, 0), NPTS - 32);
        const float4 c = d_spts[base + lane];
        const float dx = pq.x - c.x, dy = pq.y - c.y, dz = pq.z - c.z;
        float v = fmaf(dx, dx, fmaf(dy, dy, dz * dz));
        const int local = lane & 7;
        {
            float o; bool lower, asc;
            o = __shfl_xor_sync(FULLM, v, 1); lower = !(local & 1); asc = !(local & 2);
            v = (lower == asc) ? fminf(v, o) : fmaxf(v, o);
            o = __shfl_xor_sync(FULLM, v, 2); lower = !(local & 2); asc = !(local & 4);
            v = (lower == asc) ? fminf(v, o) : fmaxf(v, o);
            o = __shfl_xor_sync(FULLM, v, 1); lower = !(local & 1); asc = !(local & 4);
            v = (lower == asc) ? fminf(v, o) : fmaxf(v, o);
            o = __shfl_xor_sync(FULLM, v, 4); lower = !(local & 4);
            v = lower ? fminf(v, o) : fmaxf(v, o);
            o = __shfl_xor_sync(FULLM, v, 2); lower = !(local & 2);
            v = lower ? fminf(v, o) : fmaxf(v, o);
            o = __shfl_xor_sync(FULLM, v, 1); lower = !(local & 1);
            v = lower ? fminf(v, o) : fmaxf(v, o);
        }
        float m3 = __shfl_sync(FULLM, v, (lane & ~7) + 3);   // group's 4th smallest
        m3 = fmaxf(m3, __shfl_xor_sync(FULLM, m3, 8));
        m3 = fmaxf(m3, __shfl_xor_sync(FULLM, m3, 16));
        thresh = m3;
    }

    for (int m = 0; m < G; m++) {
        const int x0 = max(cx - m, 0), x1 = min(cx + m, G - 1);
        const int y0 = max(cy - m, 0), y1 = min(cy + m, G - 1);
        const int z0 = max(cz - m, 0), z1 = min(cz + m, G - 1);
        for (int z = z0; z <= z1; z++) {
            const bool zs = (z == cz - m) || (z == cz + m);
            for (int y = y0; y <= y1; y++) {
                const bool edge = zs || (y == cy - m) || (y == cy + m);
                const int rowc = (z * G + y) * G;
                if (edge) {
                    warp_scan_range(d_cellStart[rowc + x0], d_cellStart[rowc + x1 + 1],
                                    lane, pq.x, pq.y, pq.z, e, ei, thresh);
                } else {
                    if (cx - m >= 0)
                        warp_scan_range(d_cellStart[rowc + cx - m], d_cellStart[rowc + cx - m + 1],
                                        lane, pq.x, pq.y, pq.z, e, ei, thresh);
                    if (cx + m <= G - 1)
                        warp_scan_range(d_cellStart[rowc + cx + m], d_cellStart[rowc + cx + m + 1],
                                        lane, pq.x, pq.y, pq.z, e, ei, thresh);
                }
            }
        }
        const float bound = (float)m * HCELL;
        const float e15 = __shfl_sync(FULLM, e, 15);
        if (e15 < bound * bound) break;
    }

    // softmax of -sqrt(e) over lanes 0..15 (e sorted ascending -> max(-d) at lane 0)
    const float d = sqrtf(fmaxf(e, 1e-12f));
    const float d0 = __shfl_sync(FULLM, d, 0);
    float ex = (lane < KNN) ? expf(d0 - d) : 0.f;
    float ssum = ex;
    #pragma unroll
    for (int t = 8; t > 0; t >>= 1) ssum += __shfl_xor_sync(FULLM, ssum, t);

    if (lane < KNN) {
        const int orig = d_sidx[s];
        d_knn[orig * KNN + lane] = d_sidx[ei];
        d_wgt[orig * KNN + lane] = ex / ssum;
    }
}

// ---------------- fused MLP mega-kernel ----------------
#define PITCH 68
#define OFS_CF   0
#define OFS_BIG  (128 * PITCH)
#define OFS_BS   (384 * PITCH)
#define OFS_AS0  (OFS_BIG + 192 * PITCH)
#define SMEM_MLP (400 * PITCH * 4)

__device__ void mlp_layer(const float* __restrict__ As, int K, int k3pad,
                          const float* __restrict__ W, const float* __restrict__ bias,
                          int Nc, int act, float* Cs, float* gout, int m0, float* Bs)
{
    const int tid = threadIdx.x;
    const int tcol = tid & 15, trow = tid >> 4;
    for (int n0 = 0; n0 < Nc; n0 += 64) {
        float acc[4][4];
        #pragma unroll
        for (int i = 0; i < 4; i++)
            #pragma unroll
            for (int j = 0; j < 4; j++) acc[i][j] = 0.f;

        for (int k0 = 0; k0 < K; k0 += 16) {
            __syncthreads();
            if (k3pad) {
                for (int idx = tid; idx < 16 * 64; idx += 256) {
                    int k = idx >> 6, n = idx & 63;
                    Bs[k * PITCH + n] = (k < 3) ? W[n * 3 + k] : 0.f;
                }
            } else {
                const int n = tid >> 2, kq = (tid & 3) << 2;
                const float4 w4 = *(const float4*)&W[(n0 + n) * K + k0 + kq];
                Bs[(kq + 0) * PITCH + n] = w4.x;
                Bs[(kq + 1) * PITCH + n] = w4.y;
                Bs[(kq + 2) * PITCH + n] = w4.z;
                Bs[(kq + 3) * PITCH + n] = w4.w;
            }
            __syncthreads();
            #pragma unroll
            for (int k = 0; k < 16; k++) {
                const float4 av = *(const float4*)&As[(k0 + k) * PITCH + (trow << 2)];
                const float4 bv = *(const float4*)&Bs[k * PITCH + (tcol << 2)];
                const float ar[4] = {av.x, av.y, av.z, av.w};
                const float br[4] = {bv.x, bv.y, bv.z, bv.w};
                #pragma unroll
                for (int i = 0; i < 4; i++)
                    #pragma unroll
                    for (int j = 0; j < 4; j++)
                        acc[i][j] = fmaf(ar[i], br[j], acc[i][j]);
            }
        }
        const float4 bb = *(const float4*)&bias[n0 + (tcol << 2)];
        const float bbr[4] = {bb.x, bb.y, bb.z, bb.w};
        #pragma unroll
        for (int i = 0; i < 4; i++) {
            float v[4];
            #pragma unroll
            for (int j = 0; j < 4; j++) {
                v[j] = acc[i][j] + bbr[j];
                if (act) v[j] = lrelu(v[j]);
            }
            if (gout) {
                float4 r; r.x = v[0]; r.y = v[1]; r.z = v[2]; r.w = v[3];
                *(float4*)&gout[(m0 + (trow << 2) + i) * 128 + n0 + (tcol << 2)] = r;
            }
            if (Cs) {
                #pragma unroll
                for (int j = 0; j < 4; j++)
                    Cs[(n0 + (tcol << 2) + j) * PITCH + (trow << 2) + i] = v[j];
            }
        }
    }
    __syncthreads();
}

__global__ void __launch_bounds__(256) mlp_kernel(
    const float* __restrict__ cloud, const float* __restrict__ img,
    const float* __restrict__ pc1w, const float* __restrict__ pc1b,
    const float* __restrict__ pc2w, const float* __restrict__ pc2b,
    const float* __restrict__ ps1w, const float* __restrict__ ps1b,
    const float* __restrict__ ps2w, const float* __restrict__ ps2b,
    const float* __restrict__ c1w,  const float* __restrict__ c1b,
    const float* __restrict__ c2w,  const float* __restrict__ c2b)
{
    extern __shared__ float smem[];
    float* bufCf  = smem + OFS_CF;
    float* bufBig = smem + OFS_BIG;
    float* Bs     = smem + OFS_BS;
    float* As0    = smem + OFS_AS0;
    const int tid = threadIdx.x;
    const int p0 = blockIdx.x * 64;

    if (blockIdx.y == 0) {
        for (int idx = tid; idx < 16 * 64; idx += 256) {
            int k = idx >> 6, m = idx & 63;
            As0[k * PITCH + m] = (k < 3) ? cloud[(p0 + m) * 3 + k] : 0.f;
        }
        mlp_layer(As0,    16, 1, pc1w, pc1b,  64, 1, bufBig, nullptr, p0, Bs);
        mlp_layer(bufBig, 64, 0, pc2w, pc2b, 128, 0, bufCf,  d_cf,    p0, Bs);
        mlp_layer(bufCf, 128, 0, ps1w, ps1b, 256, 1, bufBig, nullptr, p0, Bs);
        mlp_layer(bufBig,256, 0, ps2w, ps2b, 128, 0, nullptr, d_h,    p0, Bs);
    } else {
        for (int idx = tid; idx < 32 * 64; idx += 256) {
            int k = idx >> 6, m = idx & 63;
            As0[k * PITCH + m] = img[k * NPTS + p0 + m];
        }
        mlp_layer(As0,    32, 0, c1w, c1b,  64, 1, bufBig, nullptr, p0, Bs);
        mlp_layer(bufBig, 64, 0, c2w, c2b, 128, 0, nullptr, d_g,    p0, Bs);
    }
}

// ---------------- final: gather + weighted max-pool + concat + vectorized GEMV ----------------
__global__ void __launch_bounds__(256) final_kernel(const float* __restrict__ img,
                                                    const float* __restrict__ fb,
                                                    float* __restrict__ out)
{
    __shared__ float swgt[8][KNN];
    __shared__ int   sidx[8][KNN];
    __shared__ float sfin[8][416];
    const int w = threadIdx.x >> 5, lane = threadIdx.x & 31;
    const int n = blockIdx.x * 8 + w;

    if (lane < KNN) {
        swgt[w][lane] = d_wgt[n * KNN + lane];
        sidx[w][lane] = d_knn[n * KNN + lane];
    }
    __syncwarp();

    float4 sf = make_float4(-INFINITY, -INFINITY, -INFINITY, -INFINITY);
    float4 sp = make_float4(-INFINITY, -INFINITY, -INFINITY, -INFINITY);
    #pragma unroll
    for (int k = 0; k < KNN; k++) {
        const int ik = sidx[w][k];
        const float wk = swgt[w][k];
        const float4 gv = *(const float4*)&d_g[ik * 128 + (lane << 2)];
        const float4 hv = *(const float4*)&d_h[ik * 128 + (lane << 2)];
        sf.x = fmaxf(sf.x, gv.x * wk); sf.y = fmaxf(sf.y, gv.y * wk);
        sf.z = fmaxf(sf.z, gv.z * wk); sf.w = fmaxf(sf.w, gv.w * wk);
        sp.x = fmaxf(sp.x, hv.x * wk); sp.y = fmaxf(sp.y, hv.y * wk);
        sp.z = fmaxf(sp.z, hv.z * wk); sp.w = fmaxf(sp.w, hv.w * wk);
    }
    const int c4 = lane << 2;
    sfin[w][c4 + 0] = lrelu(sp.x); sfin[w][c4 + 1] = lrelu(sp.y);
    sfin[w][c4 + 2] = lrelu(sp.z); sfin[w][c4 + 3] = lrelu(sp.w);
    sfin[w][128 + lane] = lrelu(img[lane * NPTS + n]);
    sfin[w][160 + c4 + 0] = lrelu(sf.x); sfin[w][160 + c4 + 1] = lrelu(sf.y);
    sfin[w][160 + c4 + 2] = lrelu(sf.z); sfin[w][160 + c4 + 3] = lrelu(sf.w);
    const float4 cv = *(const float4*)&d_cf[n * 128 + c4];
    sfin[w][288 + c4 + 0] = lrelu(cv.x); sfin[w][288 + c4 + 1] = lrelu(cv.y);
    sfin[w][288 + c4 + 2] = lrelu(cv.z); sfin[w][288 + c4 + 3] = lrelu(cv.w);
    __syncwarp();

    float acc0 = fb[lane], acc1 = 0.f;
    #pragma unroll 8
    for (int cq = 0; cq < 104; cq++) {
        const float4 f = *(const float4*)&sfin[w][cq << 2];
        const float4 t = *(const float4*)&d_T7v[((cq << 5) + lane) << 2];
        acc0 = fmaf(f.x, t.x, acc0);
        acc1 = fmaf(f.y, t.y, acc1);
        acc0 = fmaf(f.z, t.z, acc0);
        acc1 = fmaf(f.w, t.w, acc1);
    }
    out[lane * NPTS + n] = acc0 + acc1;
}

// ---------------- launch ----------------
extern "C" void kernel_launch(void* const* d_in, const int* in_sizes, int n_in,
                              void* d_out, int out_size)
{
    const float* img   = (const float*)d_in[0];
    const float* cloud = (const float*)d_in[1];
    const float* c1w  = (const float*)d_in[2];  const float* c1b  = (const float*)d_in[3];
    const float* c2w  = (const float*)d_in[4];  const float* c2b  = (const float*)d_in[5];
    const float* ps1w = (const float*)d_in[6];  const float* ps1b = (const float*)d_in[7];
    const float* ps2w = (const float*)d_in[8];  const float* ps2b = (const float*)d_in[9];
    const float* pc1w = (const float*)d_in[10]; const float* pc1b = (const float*)d_in[11];
    const float* pc2w = (const float*)d_in[12]; const float* pc2b = (const float*)d_in[13];
    const float* finw = (const float*)d_in[14]; const float* finb = (const float*)d_in[15];
    float* out = (float*)d_out;

    static cudaStream_t s1 = nullptr;
    static cudaEvent_t evFork = nullptr, evJoin = nullptr;
    if (s1 == nullptr) {
        cudaStreamCreateWithFlags(&s1, cudaStreamNonBlocking);
        cudaEventCreateWithFlags(&evFork, cudaEventDisableTiming);
        cudaEventCreateWithFlags(&evJoin, cudaEventDisableTiming);
        cudaFuncSetAttribute(mlp_kernel, cudaFuncAttributeMaxDynamicSharedMemorySize, SMEM_MLP);
    }

    cudaEventRecord(evFork, 0);

    // main stream: gridbuild -> knn
    gridbuild_kernel<<<1, 1024>>>(cloud, finw);
    knn_warp_kernel<<<NPTS * 32 / 256, 256>>>();

    // side stream: fused 6-layer MLP
    cudaStreamWaitEvent(s1, evFork, 0);
    mlp_kernel<<<dim3(NPTS / 64, 2), 256, SMEM_MLP, s1>>>(
        cloud, img, pc1w, pc1b, pc2w, pc2b, ps1w, ps1b, ps2w, ps2b,
        c1w, c1b, c2w, c2b);
    cudaEventRecord(evJoin, s1);

    cudaStreamWaitEvent(0, evJoin, 0);
    final_kernel<<<NPTS / 8, 256>>>(img, finb, out);
}

// round 13
// speedup vs baseline: 1.2233x; 1.1295x over previous
#include <cuda_runtime.h>
#include <cuda_bf16.h>
#include <math.h>

#define NPTS 16384
#define KNN  16
#define G    12
#define GC   (G * G * G)     // 1728 cells, ~9.5 pts/cell
#define HCELL (1.0f / G)
#define FULLM 0xffffffffu

// ---------------- scratch (device globals, no allocations) ----------------
__device__ float4 d_pts4[NPTS];
__device__ float  d_T7v[104 * 32 * 4];   // (c4, j, q) <- finw[j][4*c4+q]
__device__ float  d_cf[NPTS * 128];
__device__ float  d_g [NPTS * 128];
__device__ float  d_h [NPTS * 128];
__device__ int    d_knn[NPTS * KNN];
__device__ float  d_wgt[NPTS * KNN];
__device__ int    d_cellStart[GC + 1];
__device__ int    d_ptCell[NPTS];
__device__ float4 d_spts[NPTS];
__device__ int    d_sidx[NPTS];

__device__ __forceinline__ float lrelu(float x) { return x > 0.f ? x : 0.01f * x; }

// ---------------- gridbuild: hist + scan + scatter + T7v, ONE block ----------------
__global__ void __launch_bounds__(1024) gridbuild_kernel(const float* __restrict__ cloud,
                                                         const float* __restrict__ finw)
{
    __shared__ int scnt[GC];
    __shared__ int ssum[512];
    const int tid = threadIdx.x;

    for (int c = tid; c < GC; c += 1024) scnt[c] = 0;
    __syncthreads();

    for (int n = tid; n < NPTS; n += 1024) {
        float x = cloud[n * 3 + 0], y = cloud[n * 3 + 1], z = cloud[n * 3 + 2];
        d_pts4[n] = make_float4(x, y, z, x * x + y * y + z * z);
        int cx = min(G - 1, max(0, (int)(x * G)));
        int cy = min(G - 1, max(0, (int)(y * G)));
        int cz = min(G - 1, max(0, (int)(z * G)));
        int c = (cz * G + cy) * G + cx;
        d_ptCell[n] = c;
        atomicAdd(&scnt[c], 1);
    }
    __syncthreads();

    int c0 = 0, c1 = 0, c2 = 0, c3 = 0, s = 0;
    if (tid < 512) {
        if (4 * tid < GC) {
            c0 = scnt[4 * tid + 0]; c1 = scnt[4 * tid + 1];
            c2 = scnt[4 * tid + 2]; c3 = scnt[4 * tid + 3];
        }
        s = c0 + c1 + c2 + c3;
        ssum[tid] = s;
    }
    __syncthreads();
    for (int off = 1; off < 512; off <<= 1) {
        int v = 0;
        if (tid < 512 && tid >= off) v = ssum[tid - off];
        __syncthreads();
        if (tid < 512) ssum[tid] += v;
        __syncthreads();
    }
    if (tid < 512 && 4 * tid < GC) {
        int excl = ssum[tid] - s;
        d_cellStart[4 * tid + 0] = excl;
        d_cellStart[4 * tid + 1] = excl + c0;
        d_cellStart[4 * tid + 2] = excl + c0 + c1;
        d_cellStart[4 * tid + 3] = excl + c0 + c1 + c2;
        scnt[4 * tid + 0] = excl;
        scnt[4 * tid + 1] = excl + c0;
        scnt[4 * tid + 2] = excl + c0 + c1;
        scnt[4 * tid + 3] = excl + c0 + c1 + c2;
    }
    if (tid == 511) d_cellStart[GC] = ssum[511];
    __syncthreads();

    for (int n = tid; n < NPTS; n += 1024) {
        const int c = d_ptCell[n];
        const int pos = atomicAdd(&scnt[c], 1);
        d_spts[pos] = d_pts4[n];
        d_sidx[pos] = n;
    }

    // T7v: finw [32,416] -> [104][32][4]
    for (int t = tid; t < 104 * 32 * 4; t += 1024) {
        int c4 = t >> 7, j = (t >> 2) & 31, q = t & 3;
        d_T7v[t] = finw[j * 416 + (c4 << 2) + q];
    }
}

// ---------------- KNN: one WARP per query, distributed top-16 + softmax ----------------
__device__ __forceinline__ void warp_scan_range(int st, int en, int lane,
                                                float qx, float qy, float qz,
                                                float& e, int& ei, float& thresh)
{
    const int nb = (en - st + 31) >> 5;
    for (int b = 0; b < nb; b++) {
        const int p = st + (b << 5) + lane;
        float dcand = INFINITY;
        if (p < en) {
            const float4 c = d_spts[p];
            const float dx = qx - c.x, dy = qy - c.y, dz = qz - c.z;
            dcand = fmaf(dx, dx, fmaf(dy, dy, dz * dz));
        }
        unsigned mask = __ballot_sync(FULLM, dcand <= thresh);
        while (mask) {
            const int src = __ffs(mask) - 1;
            mask &= mask - 1;
            const float v = __shfl_sync(FULLM, dcand, src);
            const int  vi = __shfl_sync(FULLM, p,     src);
            if (v <= thresh) {              // uniform
                const unsigned le = __ballot_sync(FULLM, e <= v) & 0xFFFFu;
                const int pos = __popc(le);
                const float pe = __shfl_up_sync(FULLM, e, 1);
                const int  pei = __shfl_up_sync(FULLM, ei, 1);
                if (lane > pos) { e = pe; ei = pei; }
                if (lane == pos) { e = v; ei = vi; }
                thresh = fminf(thresh, __shfl_sync(FULLM, e, 15));
            }
        }
    }
}

__global__ void __launch_bounds__(256) knn_warp_kernel()
{
    const int lane = threadIdx.x & 31;
    const int s = (blockIdx.x * 256 + threadIdx.x) >> 5;   // query = sorted position
    const float4 pq = d_spts[s];
    const int cx = min(G - 1, max(0, (int)(pq.x * G)));
    const int cy = min(G - 1, max(0, (int)(pq.y * G)));
    const int cz = min(G - 1, max(0, (int)(pq.z * G)));

    float e = INFINITY; int ei = 0;
    // seed thresh: provable upper bound on kd15 from 32 sorted-order neighbors
    float thresh;
    {
        const int base = min(max(s - 15, 0), NPTS - 32);
        const float4 c = d_spts[base + lane];
        const float dx = pq.x - c.x, dy = pq.y - c.y, dz = pq.z - c.z;
        float v = fmaf(dx, dx, fmaf(dy, dy, dz * dz));
        const int local = lane & 7;
        {
            float o; bool lower, asc;
            o = __shfl_xor_sync(FULLM, v, 1); lower = !(local & 1); asc = !(local & 2);
            v = (lower == asc) ? fminf(v, o) : fmaxf(v, o);
            o = __shfl_xor_sync(FULLM, v, 2); lower = !(local & 2); asc = !(local & 4);
            v = (lower == asc) ? fminf(v, o) : fmaxf(v, o);
            o = __shfl_xor_sync(FULLM, v, 1); lower = !(local & 1); asc = !(local & 4);
            v = (lower == asc) ? fminf(v, o) : fmaxf(v, o);
            o = __shfl_xor_sync(FULLM, v, 4); lower = !(local & 4);
            v = lower ? fminf(v, o) : fmaxf(v, o);
            o = __shfl_xor_sync(FULLM, v, 2); lower = !(local & 2);
            v = lower ? fminf(v, o) : fmaxf(v, o);
            o = __shfl_xor_sync(FULLM, v, 1); lower = !(local & 1);
            v = lower ? fminf(v, o) : fmaxf(v, o);
        }
        float m3 = __shfl_sync(FULLM, v, (lane & ~7) + 3);   // group's 4th smallest
        m3 = fmaxf(m3, __shfl_xor_sync(FULLM, m3, 8));
        m3 = fmaxf(m3, __shfl_xor_sync(FULLM, m3, 16));
        thresh = m3;
    }

    for (int m = 0; m < G; m++) {
        const int x0 = max(cx - m, 0), x1 = min(cx + m, G - 1);
        const int y0 = max(cy - m, 0), y1 = min(cy + m, G - 1);
        const int z0 = max(cz - m, 0), z1 = min(cz + m, G - 1);
        for (int z = z0; z <= z1; z++) {
            const bool zs = (z == cz - m) || (z == cz + m);
            for (int y = y0; y <= y1; y++) {
                const bool edge = zs || (y == cy - m) || (y == cy + m);
                const int rowc = (z * G + y) * G;
                if (edge) {
                    warp_scan_range(d_cellStart[rowc + x0], d_cellStart[rowc + x1 + 1],
                                    lane, pq.x, pq.y, pq.z, e, ei, thresh);
                } else {
                    if (cx - m >= 0)
                        warp_scan_range(d_cellStart[rowc + cx - m], d_cellStart[rowc + cx - m + 1],
                                        lane, pq.x, pq.y, pq.z, e, ei, thresh);
                    if (cx + m <= G - 1)
                        warp_scan_range(d_cellStart[rowc + cx + m], d_cellStart[rowc + cx + m + 1],
                                        lane, pq.x, pq.y, pq.z, e, ei, thresh);
                }
            }
        }
        const float bound = (float)m * HCELL;
        const float e15 = __shfl_sync(FULLM, e, 15);
        if (e15 < bound * bound) break;
    }

    // softmax of -sqrt(e) over lanes 0..15 (e sorted ascending -> max(-d) at lane 0)
    const float d = sqrtf(fmaxf(e, 1e-12f));
    const float d0 = __shfl_sync(FULLM, d, 0);
    float ex = (lane < KNN) ? expf(d0 - d) : 0.f;
    float ssum = ex;
    #pragma unroll
    for (int t = 8; t > 0; t >>= 1) ssum += __shfl_xor_sync(FULLM, ssum, t);

    if (lane < KNN) {
        const int orig = d_sidx[s];
        d_knn[orig * KNN + lane] = d_sidx[ei];
        d_wgt[orig * KNN + lane] = ex / ssum;
    }
}

// ---------------- fused MLP mega-kernel ----------------
#define PITCH 68
#define OFS_CF   0
#define OFS_BIG  (128 * PITCH)
#define OFS_BS   (384 * PITCH)
#define OFS_AS0  (OFS_BIG + 192 * PITCH)
#define SMEM_MLP (400 * PITCH * 4)

__device__ void mlp_layer(const float* __restrict__ As, int K, int k3pad,
                          const float* __restrict__ W, const float* __restrict__ bias,
                          int Nc, int act, float* Cs, float* gout, int m0, float* Bs)
{
    const int tid = threadIdx.x;
    const int tcol = tid & 15, trow = tid >> 4;
    for (int n0 = 0; n0 < Nc; n0 += 64) {
        float acc[4][4];
        #pragma unroll
        for (int i = 0; i < 4; i++)
            #pragma unroll
            for (int j = 0; j < 4; j++) acc[i][j] = 0.f;

        for (int k0 = 0; k0 < K; k0 += 16) {
            __syncthreads();
            if (k3pad) {
                for (int idx = tid; idx < 16 * 64; idx += 256) {
                    int k = idx >> 6, n = idx & 63;
                    Bs[k * PITCH + n] = (k < 3) ? W[n * 3 + k] : 0.f;
                }
            } else {
                const int n = tid >> 2, kq = (tid & 3) << 2;
                const float4 w4 = *(const float4*)&W[(n0 + n) * K + k0 + kq];
                Bs[(kq + 0) * PITCH + n] = w4.x;
                Bs[(kq + 1) * PITCH + n] = w4.y;
                Bs[(kq + 2) * PITCH + n] = w4.z;
                Bs[(kq + 3) * PITCH + n] = w4.w;
            }
            __syncthreads();
            #pragma unroll
            for (int k = 0; k < 16; k++) {
                const float4 av = *(const float4*)&As[(k0 + k) * PITCH + (trow << 2)];
                const float4 bv = *(const float4*)&Bs[k * PITCH + (tcol << 2)];
                const float ar[4] = {av.x, av.y, av.z, av.w};
                const float br[4] = {bv.x, bv.y, bv.z, bv.w};
                #pragma unroll
                for (int i = 0; i < 4; i++)
                    #pragma unroll
                    for (int j = 0; j < 4; j++)
                        acc[i][j] = fmaf(ar[i], br[j], acc[i][j]);
            }
        }
        const float4 bb = *(const float4*)&bias[n0 + (tcol << 2)];
        const float bbr[4] = {bb.x, bb.y, bb.z, bb.w};
        #pragma unroll
        for (int i = 0; i < 4; i++) {
            float v[4];
            #pragma unroll
            for (int j = 0; j < 4; j++) {
                v[j] = acc[i][j] + bbr[j];
                if (act) v[j] = lrelu(v[j]);
            }
            if (gout) {
                float4 r; r.x = v[0]; r.y = v[1]; r.z = v[2]; r.w = v[3];
                *(float4*)&gout[(m0 + (trow << 2) + i) * 128 + n0 + (tcol << 2)] = r;
            }
            if (Cs) {
                #pragma unroll
                for (int j = 0; j < 4; j++)
                    Cs[(n0 + (tcol << 2) + j) * PITCH + (trow << 2) + i] = v[j];
            }
        }
    }
    __syncthreads();
}

__global__ void __launch_bounds__(256) mlp_kernel(
    const float* __restrict__ cloud, const float* __restrict__ img,
    const float* __restrict__ pc1w, const float* __restrict__ pc1b,
    const float* __restrict__ pc2w, const float* __restrict__ pc2b,
    const float* __restrict__ ps1w, const float* __restrict__ ps1b,
    const float* __restrict__ ps2w, const float* __restrict__ ps2b,
    const float* __restrict__ c1w,  const float* __restrict__ c1b,
    const float* __restrict__ c2w,  const float* __restrict__ c2b)
{
    extern __shared__ float smem[];
    float* bufCf  = smem + OFS_CF;
    float* bufBig = smem + OFS_BIG;
    float* Bs     = smem + OFS_BS;
    float* As0    = smem + OFS_AS0;
    const int tid = threadIdx.x;
    const int p0 = blockIdx.x * 64;

    if (blockIdx.y == 0) {
        for (int idx = tid; idx < 16 * 64; idx += 256) {
            int k = idx >> 6, m = idx & 63;
            As0[k * PITCH + m] = (k < 3) ? cloud[(p0 + m) * 3 + k] : 0.f;
        }
        mlp_layer(As0,    16, 1, pc1w, pc1b,  64, 1, bufBig, nullptr, p0, Bs);
        mlp_layer(bufBig, 64, 0, pc2w, pc2b, 128, 0, bufCf,  d_cf,    p0, Bs);
        mlp_layer(bufCf, 128, 0, ps1w, ps1b, 256, 1, bufBig, nullptr, p0, Bs);
        mlp_layer(bufBig,256, 0, ps2w, ps2b, 128, 0, nullptr, d_h,    p0, Bs);
    } else {
        for (int idx = tid; idx < 32 * 64; idx += 256) {
            int k = idx >> 6, m = idx & 63;
            As0[k * PITCH + m] = img[k * NPTS + p0 + m];
        }
        mlp_layer(As0,    32, 0, c1w, c1b,  64, 1, bufBig, nullptr, p0, Bs);
        mlp_layer(bufBig, 64, 0, c2w, c2b, 128, 0, nullptr, d_g,    p0, Bs);
    }
}

// ---------------- final: gather + weighted max-pool + concat + block-coop GEMM ----------------
__global__ void __launch_bounds__(256) final_kernel(const float* __restrict__ img,
                                                    const float* __restrict__ fb,
                                                    float* __restrict__ out)
{
    __shared__ float swgt[8][KNN];
    __shared__ int   sidx[8][KNN];
    __shared__ float sfin[8][416];
    __shared__ float spart[8][8][32];   // [warp][point][outchan]
    const int w = threadIdx.x >> 5, lane = threadIdx.x & 31;
    const int n = blockIdx.x * 8 + w;

    // phase 1: warp w builds point w's 416-vector
    if (lane < KNN) {
        swgt[w][lane] = d_wgt[n * KNN + lane];
        sidx[w][lane] = d_knn[n * KNN + lane];
    }
    __syncwarp();

    float4 sf = make_float4(-INFINITY, -INFINITY, -INFINITY, -INFINITY);
    float4 sp = make_float4(-INFINITY, -INFINITY, -INFINITY, -INFINITY);
    #pragma unroll
    for (int k = 0; k < KNN; k++) {
        const int ik = sidx[w][k];
        const float wk = swgt[w][k];
        const float4 gv = *(const float4*)&d_g[ik * 128 + (lane << 2)];
        const float4 hv = *(const float4*)&d_h[ik * 128 + (lane << 2)];
        sf.x = fmaxf(sf.x, gv.x * wk); sf.y = fmaxf(sf.y, gv.y * wk);
        sf.z = fmaxf(sf.z, gv.z * wk); sf.w = fmaxf(sf.w, gv.w * wk);
        sp.x = fmaxf(sp.x, hv.x * wk); sp.y = fmaxf(sp.y, hv.y * wk);
        sp.z = fmaxf(sp.z, hv.z * wk); sp.w = fmaxf(sp.w, hv.w * wk);
    }
    const int c4 = lane << 2;
    sfin[w][c4 + 0] = lrelu(sp.x); sfin[w][c4 + 1] = lrelu(sp.y);
    sfin[w][c4 + 2] = lrelu(sp.z); sfin[w][c4 + 3] = lrelu(sp.w);
    sfin[w][128 + lane] = lrelu(img[lane * NPTS + n]);
    sfin[w][160 + c4 + 0] = lrelu(sf.x); sfin[w][160 + c4 + 1] = lrelu(sf.y);
    sfin[w][160 + c4 + 2] = lrelu(sf.z); sfin[w][160 + c4 + 3] = lrelu(sf.w);
    const float4 cv = *(const float4*)&d_cf[n * 128 + c4];
    sfin[w][288 + c4 + 0] = lrelu(cv.x); sfin[w][288 + c4 + 1] = lrelu(cv.y);
    sfin[w][288 + c4 + 2] = lrelu(cv.z); sfin[w][288 + c4 + 3] = lrelu(cv.w);
    __syncthreads();

    // phase 2: warp w covers c4-slice [13w, 13w+13) for ALL 8 points
    // (weight stream loaded once per block-slice instead of once per warp)
    {
        float acc[8];
        #pragma unroll
        for (int p = 0; p < 8; p++) acc[p] = 0.f;
        const int cq0 = w * 13;
        #pragma unroll
        for (int i = 0; i < 13; i++) {
            const int cq = cq0 + i;
            const float4 t = *(const float4*)&d_T7v[((cq << 5) + lane) << 2];
            #pragma unroll
            for (int p = 0; p < 8; p++) {
                const float4 f = *(const float4*)&sfin[p][cq << 2];
                acc[p] = fmaf(f.x, t.x, fmaf(f.y, t.y, fmaf(f.z, t.z, fmaf(f.w, t.w, acc[p]))));
            }
        }
        #pragma unroll
        for (int p = 0; p < 8; p++) spart[w][p][lane] = acc[p];
    }
    __syncthreads();

    // phase 3: thread (p = w, chan = lane) reduces 8 partials
    {
        float s = fb[lane];
        #pragma unroll
        for (int w2 = 0; w2 < 8; w2++) s += spart[w2][w][lane];
        out[lane * NPTS + blockIdx.x * 8 + w] = s;
    }
}

// ---------------- launch ----------------
extern "C" void kernel_launch(void* const* d_in, const int* in_sizes, int n_in,
                              void* d_out, int out_size)
{
    const float* img   = (const float*)d_in[0];
    const float* cloud = (const float*)d_in[1];
    const float* c1w  = (const float*)d_in[2];  const float* c1b  = (const float*)d_in[3];
    const float* c2w  = (const float*)d_in[4];  const float* c2b  = (const float*)d_in[5];
    const float* ps1w = (const float*)d_in[6];  const float* ps1b = (const float*)d_in[7];
    const float* ps2w = (const float*)d_in[8];  const float* ps2b = (const float*)d_in[9];
    const float* pc1w = (const float*)d_in[10]; const float* pc1b = (const float*)d_in[11];
    const float* pc2w = (const float*)d_in[12]; const float* pc2b = (const float*)d_in[13];
    const float* finw = (const float*)d_in[14]; const float* finb = (const float*)d_in[15];
    float* out = (float*)d_out;

    static cudaStream_t s1 = nullptr;
    static cudaEvent_t evFork = nullptr, evJoin = nullptr;
    if (s1 == nullptr) {
        cudaStreamCreateWithFlags(&s1, cudaStreamNonBlocking);
        cudaEventCreateWithFlags(&evFork, cudaEventDisableTiming);
        cudaEventCreateWithFlags(&evJoin, cudaEventDisableTiming);
        cudaFuncSetAttribute(mlp_kernel, cudaFuncAttributeMaxDynamicSharedMemorySize, SMEM_MLP);
    }

    cudaEventRecord(evFork, 0);

    // main stream: gridbuild -> knn
    gridbuild_kernel<<<1, 1024>>>(cloud, finw);
    knn_warp_kernel<<<NPTS * 32 / 256, 256>>>();

    // side stream: fused 6-layer MLP
    cudaStreamWaitEvent(s1, evFork, 0);
    mlp_kernel<<<dim3(NPTS / 64, 2), 256, SMEM_MLP, s1>>>(
        cloud, img, pc1w, pc1b, pc2w, pc2b, ps1w, ps1b, ps2w, ps2b,
        c1w, c1b, c2w, c2b);
    cudaEventRecord(evJoin, s1);

    cudaStreamWaitEvent(0, evJoin, 0);
    final_kernel<<<NPTS / 8, 256>>>(img, finb, out);
}